// round 6
// baseline (speedup 1.0000x reference)
#include <cuda_runtime.h>

#define NB 32      // batch
#define NA 286     // atoms
#define CIN 23
#define CINP 24    // padded
#define HH 100     // hidden width of radial MLP
#define BPAD 288   // padded atom count
#define NCHUNK 3   // b-chunks (96 b each)

// ---------------- packed f32x2 helpers (sm_103a) ----------------
#define FMA2(d, a, b, c) \
    asm("fma.rn.f32x2 %0, %1, %2, %3;" : "=l"(d) : "l"(a), "l"(b), "l"(c))
#define ADD2(d, a, b) \
    asm("add.rn.f32x2 %0, %1, %2;" : "=l"(d) : "l"(a), "l"(b))

__device__ __forceinline__ unsigned long long pk2(float lo, float hi) {
    unsigned long long d;
    asm("mov.b64 %0, {%1, %2};" : "=l"(d) : "r"(__float_as_uint(lo)), "r"(__float_as_uint(hi)));
    return d;
}
__device__ __forceinline__ void unpk2(unsigned long long v, float& lo, float& hi) {
    unsigned int l, h;
    asm("mov.b64 {%0, %1}, %2;" : "=r"(l), "=r"(h) : "l"(v));
    lo = __uint_as_float(l); hi = __uint_as_float(h);
}
__device__ __forceinline__ unsigned long long dup2(float w) {
    unsigned long long u = __float_as_uint(w);
    return (u << 32) | u;
}

// ---------------- device scratch ----------------
__device__ unsigned long long g_gT2[NB][HH][BPAD];  // dup {g,g} per (z,k,b)
__device__ ulonglong4        g_u[NB][BPAD];         // dup'd u vector per (z,b): W1^T@g[b] (+bias row)
__device__ ulonglong2        g_w1dup[HH][2];        // [k][0]={wx2,wy2} [k][1]={wz2,wb2}
__device__ float             g_cz[NB];
__device__ float4            g_geom4[NB][BPAD];     // (x,y,z,0), zero-padded
__device__ float             g_fpart[NCHUNK][NB][NA];

// ---------------- merged prep kernel ----------------
// grid (10, NB), 256 thr. bx<9: g-tile (32 b's) + per-b u vector. bx==9: cz, geom4, (z==0) w1 pack.
__global__ void __launch_bounds__(256) k_prep(const float* __restrict__ features,
                                              const float* __restrict__ geometry,
                                              const float* __restrict__ rW1,
                                              const float* __restrict__ rb1,
                                              const float* __restrict__ rW2,
                                              const float* __restrict__ rb2) {
    const int z = blockIdx.y;
    const int tid = threadIdx.x;

    if (blockIdx.x == 9) {
        if (z == 0 && tid < HH) {
            float wx = rW1[tid], wy = rW1[HH + tid], wz = rW1[2 * HH + tid], wb = rb1[tid];
            g_w1dup[tid][0] = make_ulonglong2(dup2(wx), dup2(wy));
            g_w1dup[tid][1] = make_ulonglong2(dup2(wz), dup2(wb));
        }
        for (int b = tid; b < BPAD; b += 256) {
            float4 v = make_float4(0.f, 0.f, 0.f, 0.f);
            if (b < NA) {
                const float* p = geometry + (z * NA + b) * 3;
                v.x = p[0]; v.y = p[1]; v.z = p[2];
            }
            g_geom4[z][b] = v;
        }
        __shared__ float red[256];
        float s = 0.f;
        const int TOT = NA * CIN;
        for (int i = tid; i < TOT; i += 256)
            s = fmaf(rb2[i % CIN], features[z * TOT + i], s);
        red[tid] = s;
        __syncthreads();
        for (int off = 128; off; off >>= 1) {
            if (tid < off) red[tid] += red[tid + off];
            __syncthreads();
        }
        if (tid == 0) g_cz[z] = red[0];
        return;
    }

    // --- g tile + u ---
    __shared__ float fs24[32][CINP];          // padded features tile
    __shared__ float w2s24[HH][CINP];         // padded rW2
    __shared__ float gsh[HH][33];             // stride 33: conflict-free for u-loop
    __shared__ float w1sh[4][HH];
    const int bt = blockIdx.x * 32;

    for (int i = tid; i < 32 * CINP; i += 256) {
        int b = i / CINP, j = i % CINP;
        int gb = bt + b;
        fs24[b][j] = (j < CIN && gb < NA) ? features[(z * NA + gb) * CIN + j] : 0.f;
    }
    for (int i = tid; i < HH * CINP; i += 256) {
        int k = i / CINP, j = i % CINP;
        w2s24[k][j] = (j < CIN) ? rW2[k * CIN + j] : 0.f;
    }
    for (int i = tid; i < 4 * HH; i += 256) {
        int c = i / HH, k = i % HH;
        w1sh[c][k] = (c < 3) ? rW1[c * HH + k] : rb1[k];
    }
    __syncthreads();

    // each thread: fixed b = tid&31, k = (tid>>5) + 8n ; features row in registers (float4 x6)
    {
        const int b = tid & 31;
        float4 fr[6];
        #pragma unroll
        for (int q = 0; q < 6; q++) fr[q] = *(const float4*)&fs24[b][q * 4];
        for (int k = (tid >> 5); k < HH; k += 8) {
            const float4* wp = (const float4*)w2s24[k];
            float s = 0.f;
            #pragma unroll
            for (int q = 0; q < 6; q++) {
                float4 w = wp[q];
                s = fmaf(w.x, fr[q].x, s);
                s = fmaf(w.y, fr[q].y, s);
                s = fmaf(w.z, fr[q].z, s);
                s = fmaf(w.w, fr[q].w, s);
            }
            gsh[k][b] = s;
            g_gT2[z][k][bt + b] = dup2(s);
        }
    }
    __syncthreads();

    // u_c[b] = sum_k w1sh[c][k] * gsh[k][b]; 2 threads per output over k-halves
    {
        int out = tid >> 1, half = tid & 1;
        int c = out >> 5, b = out & 31;
        float s = 0.f;
        int k0 = half * 50;
        #pragma unroll 10
        for (int k = k0; k < k0 + 50; k++)
            s = fmaf(w1sh[c][k], gsh[k][b], s);
        s += __shfl_xor_sync(0xffffffffu, s, 1);
        if (half == 0)
            ((unsigned long long*)&g_u[z][bt + b])[c] = dup2(s);
    }
}

// ---------------- basis: cos(pi/2 * t) via even poly ----------------
__device__ __forceinline__ float cospi_half(float t) {
    float y = t * t;
    float p = fmaf(9.1926027e-4f, y, -2.0863481e-2f);
    p = fmaf(p, y,  2.5366951e-1f);
    p = fmaf(p, y, -1.2337006f);
    p = fmaf(p, y,  1.0f);
    return p;
}
__device__ __forceinline__ void basis3(float r, float& p0, float& p1, float& p2) {
    const float inv = 1.0f / 1.5f;
    float zz = r * inv;
    float t0 = 1.f - fmaxf(2.f - fmaxf(zz + 1.f, 0.f), 0.f);
    float t1 = 1.f - fmaxf(2.f - fmaxf(zz,       0.f), 0.f);
    float t2 = 1.f - fmaxf(2.f - fmaxf(zz - 1.f, 0.f), 0.f);
    p0 = cospi_half(t0);
    p1 = cospi_half(t1);
    p2 = cospi_half(t2);
}

// ---------------- main kernel ----------------
// grid (9 a-tiles, NCHUNK b-chunks, NB z). 128 thr = 4 warps, 8 a's/warp (4 packed pairs).
// Each block reduces over 96 b's (3 tiles) and writes its partial to g_fpart[chunk].
__global__ void __launch_bounds__(128) k_main() {
    const int z     = blockIdx.z;
    const int chunk = blockIdx.y;
    const int warp  = threadIdx.x >> 5;
    const int lane  = threadIdx.x & 31;
    const int tid   = threadIdx.x;
    const int a0    = blockIdx.x * 32 + warp * 8;

    __shared__ ulonglong2         w1s2[HH][2];
    __shared__ unsigned long long gs2[HH][32];

    for (int i = tid; i < HH * 2; i += 128)
        ((ulonglong2*)w1s2)[i] = ((const ulonglong2*)g_w1dup)[i];

    float ax[8], ay[8], az[8];
    #pragma unroll
    for (int u = 0; u < 8; u++) {
        int a = a0 + u; if (a > NA - 1) a = NA - 1;   // clamp; extras never written
        float4 p = g_geom4[z][a];
        ax[u] = p.x; ay[u] = p.y; az[u] = p.z;
    }

    unsigned long long acc[4];
    #pragma unroll
    for (int p = 0; p < 4; p++) acc[p] = 0ull;

    const int bt0 = chunk * 96;
    for (int bt = bt0; bt < bt0 + 96; bt += 32) {
        __syncthreads();
        for (int i = tid; i < HH * 32; i += 128)
            gs2[i >> 5][i & 31] = g_gT2[z][i >> 5][bt + (i & 31)];
        __syncthreads();

        const float4 bg = g_geom4[z][bt + lane];
        const ulonglong4 ud = g_u[z][bt + lane];

        unsigned long long P0[4], P1[4], P2[4];
        #pragma unroll
        for (int p = 0; p < 4; p++) {
            float q0a, q1a, q2a, q0b, q1b, q2b;
            {
                float dx = bg.x - ax[2*p], dy = bg.y - ay[2*p], dz = bg.z - az[2*p];
                float r = sqrtf(fmaf(dx, dx, fmaf(dy, dy, fmaf(dz, dz, 1e-12f))));
                basis3(r, q0a, q1a, q2a);
            }
            {
                float dx = bg.x - ax[2*p+1], dy = bg.y - ay[2*p+1], dz = bg.z - az[2*p+1];
                float r = sqrtf(fmaf(dx, dx, fmaf(dy, dy, fmaf(dz, dz, 1e-12f))));
                basis3(r, q0b, q1b, q2b);
            }
            P0[p] = pk2(q0a, q0b); P1[p] = pk2(q1a, q1b); P2[p] = pk2(q2a, q2b);
            // linear half of relu split: p~ . u[b] (bias row via ud.w)
            unsigned long long lin;
            FMA2(lin, P0[p], ud.x, ud.w);
            FMA2(lin, P1[p], ud.y, lin);
            FMA2(lin, P2[p], ud.z, lin);
            ADD2(acc[p], acc[p], lin);
        }

        #pragma unroll 10
        for (int k = 0; k < HH; k++) {
            ulonglong2 cA = w1s2[k][0];   // {wx2, wy2}
            ulonglong2 cB = w1s2[k][1];   // {wz2, wb2}
            unsigned long long gd = gs2[k][lane];
            #pragma unroll
            for (int p = 0; p < 4; p++) {
                unsigned long long h;
                FMA2(h, cA.x, P0[p], cB.y);
                FMA2(h, cA.y, P1[p], h);
                FMA2(h, cB.x, P2[p], h);
                h &= 0x7FFFFFFF7FFFFFFFull;       // packed |h|
                FMA2(acc[p], h, gd, acc[p]);
            }
        }
    }

    float s[8];
    #pragma unroll
    for (int p = 0; p < 4; p++) unpk2(acc[p], s[2*p], s[2*p+1]);
    #pragma unroll
    for (int u = 0; u < 8; u++) {
        #pragma unroll
        for (int off = 16; off; off >>= 1)
            s[u] += __shfl_xor_sync(0xffffffffu, s[u], off);
    }

    if (lane == 0) {
        const float SCALE0 = 0.28209479177387814f / 16.911534525287763f;  // Y0 / sqrt(286)
        const float HALF_SCALE = 0.5f * SCALE0;
        #pragma unroll
        for (int u = 0; u < 8; u++) {
            int a = a0 + u;
            if (a < NA) g_fpart[chunk][z][a] = s[u] * HALF_SCALE;
        }
    }
}

// ---------------- head MLP: 286 -> 30 -> 10 -> 1 ----------------
__global__ void __launch_bounds__(256) k_head(const float* __restrict__ fc1W,
                                              const float* __restrict__ fc1b,
                                              const float* __restrict__ fc2W,
                                              const float* __restrict__ fc2b,
                                              const float* __restrict__ fc3W,
                                              const float* __restrict__ fc3b,
                                              float* __restrict__ out) {
    const int z = blockIdx.x;
    const int tid = threadIdx.x;
    const int warp = tid >> 5;
    const int lane = tid & 31;
    __shared__ float fsh[BPAD];
    __shared__ float h1[30];
    __shared__ float h2[10];

    const float SCALE0 = 0.28209479177387814f / 16.911534525287763f;
    const float czs = g_cz[z] * SCALE0;
    for (int i = tid; i < BPAD; i += 256)
        fsh[i] = (i < NA) ? (g_fpart[0][z][i] + g_fpart[1][z][i] + g_fpart[2][z][i] + czs) : 0.f;
    __syncthreads();

    for (int o = warp; o < 30; o += 8) {
        float w[9], f[9];
        #pragma unroll
        for (int kk = 0; kk < 9; kk++) {
            int idx = lane + 32 * kk;
            w[kk] = (idx < NA) ? __ldg(&fc1W[idx * 30 + o]) : 0.f;
            f[kk] = fsh[idx];
        }
        float ssum = 0.f;
        #pragma unroll
        for (int kk = 0; kk < 9; kk++) ssum = fmaf(w[kk], f[kk], ssum);
        #pragma unroll
        for (int off = 16; off; off >>= 1) ssum += __shfl_xor_sync(0xffffffffu, ssum, off);
        if (lane == 0) h1[o] = fmaxf(ssum + fc1b[o], 0.f);
    }
    __syncthreads();

    if (tid < 10) {
        float s = fc2b[tid];
        #pragma unroll
        for (int o = 0; o < 30; o++) s = fmaf(h1[o], fc2W[o * 10 + tid], s);
        h2[tid] = fmaxf(s, 0.f);
    }
    __syncthreads();

    if (tid == 0) {
        float s = fc3b[0];
        #pragma unroll
        for (int p = 0; p < 10; p++) s = fmaf(h2[p], fc3W[p], s);
        out[z] = s;
    }
}

// ---------------- launch ----------------
extern "C" void kernel_launch(void* const* d_in, const int* in_sizes, int n_in,
                              void* d_out, int out_size) {
    const float* features = (const float*)d_in[1];
    const float* geometry = (const float*)d_in[2];
    const float* rW1      = (const float*)d_in[3];
    const float* rb1      = (const float*)d_in[4];
    const float* rW2      = (const float*)d_in[5];
    const float* rb2      = (const float*)d_in[6];
    const float* fc1W     = (const float*)d_in[7];
    const float* fc1b     = (const float*)d_in[8];
    const float* fc2W     = (const float*)d_in[9];
    const float* fc2b     = (const float*)d_in[10];
    const float* fc3W     = (const float*)d_in[11];
    const float* fc3b     = (const float*)d_in[12];
    float* out = (float*)d_out;

    k_prep <<<dim3(10, NB), 256>>>(features, geometry, rW1, rb1, rW2, rb2);
    k_main <<<dim3(9, NCHUNK, NB), 128>>>();
    k_head <<<NB, 256>>>(fc1W, fc1b, fc2W, fc2b, fc3W, fc3b, out);
}

// round 7
// speedup vs baseline: 1.3385x; 1.3385x over previous
#include <cuda_runtime.h>

#define NB 32      // batch
#define NA 286     // atoms
#define CIN 23
#define HH 100     // hidden width of radial MLP
#define BPAD 288   // padded atom count

// ---------------- packed f32x2 helpers (sm_103a) ----------------
#define FMA2(d, a, b, c) \
    asm("fma.rn.f32x2 %0, %1, %2, %3;" : "=l"(d) : "l"(a), "l"(b), "l"(c))
#define ADD2(d, a, b) \
    asm("add.rn.f32x2 %0, %1, %2;" : "=l"(d) : "l"(a), "l"(b))

__device__ __forceinline__ unsigned long long pk2(float lo, float hi) {
    unsigned long long d;
    asm("mov.b64 %0, {%1, %2};" : "=l"(d) : "r"(__float_as_uint(lo)), "r"(__float_as_uint(hi)));
    return d;
}
__device__ __forceinline__ void unpk2(unsigned long long v, float& lo, float& hi) {
    unsigned int l, h;
    asm("mov.b64 {%0, %1}, %2;" : "=r"(l), "=r"(h) : "l"(v));
    lo = __uint_as_float(l); hi = __uint_as_float(h);
}
__device__ __forceinline__ unsigned long long dup2(float w) {
    unsigned long long u = __float_as_uint(w);
    return (u << 32) | u;
}

// ---------------- device scratch ----------------
__device__ unsigned long long g_gT2[NB][HH][BPAD];  // dup {g,g} per (z,k,b)
__device__ ulonglong4        g_u[NB][BPAD];         // dup'd u vector per (z,b): W1^T@g[b] (+bias row)
__device__ ulonglong2        g_w1dup[HH][2];        // [k][0]={wx2,wy2} [k][1]={wz2,wb2}
__device__ float             g_cz[NB];
__device__ float4            g_geom4[NB][BPAD];     // (x,y,z,0), zero-padded
__device__ float             g_feats[NB][NA];

// ---------------- merged prep kernel (identical to R5) ----------------
__global__ void __launch_bounds__(256) k_prep(const float* __restrict__ features,
                                              const float* __restrict__ geometry,
                                              const float* __restrict__ rW1,
                                              const float* __restrict__ rb1,
                                              const float* __restrict__ rW2,
                                              const float* __restrict__ rb2) {
    const int z = blockIdx.y;
    const int tid = threadIdx.x;

    if (blockIdx.x == 9) {
        if (z == 0 && tid < HH) {
            float wx = rW1[tid], wy = rW1[HH + tid], wz = rW1[2 * HH + tid], wb = rb1[tid];
            g_w1dup[tid][0] = make_ulonglong2(dup2(wx), dup2(wy));
            g_w1dup[tid][1] = make_ulonglong2(dup2(wz), dup2(wb));
        }
        for (int b = tid; b < BPAD; b += 256) {
            float4 v = make_float4(0.f, 0.f, 0.f, 0.f);
            if (b < NA) {
                const float* p = geometry + (z * NA + b) * 3;
                v.x = p[0]; v.y = p[1]; v.z = p[2];
            }
            g_geom4[z][b] = v;
        }
        __shared__ float red[256];
        float s = 0.f;
        const int TOT = NA * CIN;
        for (int i = tid; i < TOT; i += 256)
            s = fmaf(rb2[i % CIN], features[z * TOT + i], s);
        red[tid] = s;
        __syncthreads();
        for (int off = 128; off; off >>= 1) {
            if (tid < off) red[tid] += red[tid + off];
            __syncthreads();
        }
        if (tid == 0) g_cz[z] = red[0];
        return;
    }

    __shared__ float fs[32][CIN];
    __shared__ float w2s[HH * CIN];
    __shared__ float gsh[HH][32];
    const int bt = blockIdx.x * 32;

    for (int i = tid; i < 32 * CIN; i += 256) {
        int b = i / CIN, j = i % CIN;
        int gb = bt + b;
        fs[b][j] = (gb < NA) ? features[(z * NA + gb) * CIN + j] : 0.f;
    }
    for (int i = tid; i < HH * CIN; i += 256) w2s[i] = rW2[i];
    __syncthreads();

    for (int i = tid; i < HH * 32; i += 256) {
        int k = i >> 5, b = i & 31;
        float s = 0.f;
        #pragma unroll
        for (int j = 0; j < CIN; j++) s = fmaf(w2s[k * CIN + j], fs[b][j], s);
        gsh[k][b] = s;
        g_gT2[z][k][bt + b] = dup2(s);
    }
    __syncthreads();

    if (tid < 128) {
        int b = tid & 31, c = tid >> 5;
        float acc = 0.f;
        for (int k = 0; k < HH; k++) {
            float w = (c < 3) ? __ldg(&rW1[c * HH + k]) : __ldg(&rb1[k]);
            acc = fmaf(w, gsh[k][b], acc);
        }
        ((unsigned long long*)&g_u[z][bt + b])[c] = dup2(acc);
    }
}

// ---------------- basis: cos(pi/2 * t) via even poly ----------------
__device__ __forceinline__ float cospi_half(float t) {
    float y = t * t;
    float p = fmaf(9.1926027e-4f, y, -2.0863481e-2f);
    p = fmaf(p, y,  2.5366951e-1f);
    p = fmaf(p, y, -1.2337006f);
    p = fmaf(p, y,  1.0f);
    return p;
}
__device__ __forceinline__ void basis3(float r, float& p0, float& p1, float& p2) {
    const float inv = 1.0f / 1.5f;
    float zz = r * inv;
    float t0 = 1.f - fmaxf(2.f - fmaxf(zz + 1.f, 0.f), 0.f);
    float t1 = 1.f - fmaxf(2.f - fmaxf(zz,       0.f), 0.f);
    float t2 = 1.f - fmaxf(2.f - fmaxf(zz - 1.f, 0.f), 0.f);
    p0 = cospi_half(t0);
    p1 = cospi_half(t1);
    p2 = cospi_half(t2);
}

// ---------------- main kernel ----------------
// grid (9, NB), 256 thr = 8 warps. Warp w: a-group ag=w&3 (8 a's), k-half kh=w>>2.
// Full b-loop per block (no partial-sum gmem traffic). 4 warps/SMSP for latency hiding.
__global__ void __launch_bounds__(256) k_main() {
    const int z    = blockIdx.y;
    const int warp = threadIdx.x >> 5;
    const int lane = threadIdx.x & 31;
    const int tid  = threadIdx.x;
    const int ag   = warp & 3;
    const int kh   = warp >> 2;
    const int a0   = blockIdx.x * 32 + ag * 8;

    __shared__ ulonglong2         w1s2[HH][2];
    __shared__ unsigned long long gs2[HH][32];
    __shared__ float              spart[8][8];

    for (int i = tid; i < HH * 2; i += 256)
        ((ulonglong2*)w1s2)[i] = ((const ulonglong2*)g_w1dup)[i];

    float ax[8], ay[8], az[8];
    #pragma unroll
    for (int u = 0; u < 8; u++) {
        int a = a0 + u; if (a > NA - 1) a = NA - 1;   // clamp; extras never written
        float4 p = g_geom4[z][a];
        ax[u] = p.x; ay[u] = p.y; az[u] = p.z;
    }

    unsigned long long acc[4];
    #pragma unroll
    for (int p = 0; p < 4; p++) acc[p] = 0ull;

    const int k0 = kh * 50;

    for (int bt = 0; bt < NA; bt += 32) {
        __syncthreads();
        for (int i = tid; i < HH * 32; i += 256)
            gs2[i >> 5][i & 31] = g_gT2[z][i >> 5][bt + (i & 31)];
        __syncthreads();

        const float4 bg = g_geom4[z][bt + lane];

        unsigned long long P0[4], P1[4], P2[4];
        #pragma unroll
        for (int p = 0; p < 4; p++) {
            float q0a, q1a, q2a, q0b, q1b, q2b;
            {
                float dx = bg.x - ax[2*p], dy = bg.y - ay[2*p], dz = bg.z - az[2*p];
                float r = sqrtf(fmaf(dx, dx, fmaf(dy, dy, fmaf(dz, dz, 1e-12f))));
                basis3(r, q0a, q1a, q2a);
            }
            {
                float dx = bg.x - ax[2*p+1], dy = bg.y - ay[2*p+1], dz = bg.z - az[2*p+1];
                float r = sqrtf(fmaf(dx, dx, fmaf(dy, dy, fmaf(dz, dz, 1e-12f))));
                basis3(r, q0b, q1b, q2b);
            }
            P0[p] = pk2(q0a, q0b); P1[p] = pk2(q1a, q1b); P2[p] = pk2(q2a, q2b);
        }

        if (kh == 0) {
            // linear half of relu split: p~ . u[b] (bias row via ud.w) — once per pair
            const ulonglong4 ud = g_u[z][bt + lane];
            #pragma unroll
            for (int p = 0; p < 4; p++) {
                unsigned long long lin;
                FMA2(lin, P0[p], ud.x, ud.w);
                FMA2(lin, P1[p], ud.y, lin);
                FMA2(lin, P2[p], ud.z, lin);
                ADD2(acc[p], acc[p], lin);
            }
        }

        #pragma unroll 10
        for (int kk = 0; kk < 50; kk++) {
            const int k = k0 + kk;
            ulonglong2 cA = w1s2[k][0];   // {wx2, wy2}
            ulonglong2 cB = w1s2[k][1];   // {wz2, wb2}
            unsigned long long gd = gs2[k][lane];
            #pragma unroll
            for (int p = 0; p < 4; p++) {
                unsigned long long h;
                FMA2(h, cA.x, P0[p], cB.y);
                FMA2(h, cA.y, P1[p], h);
                FMA2(h, cB.x, P2[p], h);
                h &= 0x7FFFFFFF7FFFFFFFull;       // packed |h|
                FMA2(acc[p], h, gd, acc[p]);
            }
        }
    }

    float s[8];
    #pragma unroll
    for (int p = 0; p < 4; p++) unpk2(acc[p], s[2*p], s[2*p+1]);
    #pragma unroll
    for (int u = 0; u < 8; u++) {
        #pragma unroll
        for (int off = 16; off; off >>= 1)
            s[u] += __shfl_xor_sync(0xffffffffu, s[u], off);
    }
    if (lane < 8) spart[warp][lane] = s[lane];   // lane u holds... (all lanes have full sum after bfly)
    __syncthreads();

    if (tid < 32) {
        int agc = tid >> 3, u = tid & 7;
        const float SCALE0 = 0.28209479177387814f / 16.911534525287763f;  // Y0 / sqrt(286)
        const float HALF_SCALE = 0.5f * SCALE0;
        float tot = spart[agc][u] + spart[agc + 4][u];
        float czs = g_cz[z] * SCALE0;
        int a = blockIdx.x * 32 + agc * 8 + u;
        if (a < NA) g_feats[z][a] = fmaf(tot, HALF_SCALE, czs);
    }
}

// ---------------- head MLP: 286 -> 30 -> 10 -> 1 (identical to R5) ----------------
__global__ void __launch_bounds__(256) k_head(const float* __restrict__ fc1W,
                                              const float* __restrict__ fc1b,
                                              const float* __restrict__ fc2W,
                                              const float* __restrict__ fc2b,
                                              const float* __restrict__ fc3W,
                                              const float* __restrict__ fc3b,
                                              float* __restrict__ out) {
    const int z = blockIdx.x;
    const int tid = threadIdx.x;
    const int warp = tid >> 5;
    const int lane = tid & 31;
    __shared__ float fsh[BPAD];
    __shared__ float h1[30];
    __shared__ float h2[10];

    for (int i = tid; i < BPAD; i += 256) fsh[i] = (i < NA) ? g_feats[z][i] : 0.f;
    __syncthreads();

    for (int o = warp; o < 30; o += 8) {
        float w[9], f[9];
        #pragma unroll
        for (int kk = 0; kk < 9; kk++) {
            int idx = lane + 32 * kk;
            w[kk] = (idx < NA) ? __ldg(&fc1W[idx * 30 + o]) : 0.f;
            f[kk] = fsh[idx];
        }
        float ssum = 0.f;
        #pragma unroll
        for (int kk = 0; kk < 9; kk++) ssum = fmaf(w[kk], f[kk], ssum);
        #pragma unroll
        for (int off = 16; off; off >>= 1) ssum += __shfl_xor_sync(0xffffffffu, ssum, off);
        if (lane == 0) h1[o] = fmaxf(ssum + fc1b[o], 0.f);
    }
    __syncthreads();

    if (tid < 10) {
        float s = fc2b[tid];
        #pragma unroll
        for (int o = 0; o < 30; o++) s = fmaf(h1[o], fc2W[o * 10 + tid], s);
        h2[tid] = fmaxf(s, 0.f);
    }
    __syncthreads();

    if (tid == 0) {
        float s = fc3b[0];
        #pragma unroll
        for (int p = 0; p < 10; p++) s = fmaf(h2[p], fc3W[p], s);
        out[z] = s;
    }
}

// ---------------- launch ----------------
extern "C" void kernel_launch(void* const* d_in, const int* in_sizes, int n_in,
                              void* d_out, int out_size) {
    const float* features = (const float*)d_in[1];
    const float* geometry = (const float*)d_in[2];
    const float* rW1      = (const float*)d_in[3];
    const float* rb1      = (const float*)d_in[4];
    const float* rW2      = (const float*)d_in[5];
    const float* rb2      = (const float*)d_in[6];
    const float* fc1W     = (const float*)d_in[7];
    const float* fc1b     = (const float*)d_in[8];
    const float* fc2W     = (const float*)d_in[9];
    const float* fc2b     = (const float*)d_in[10];
    const float* fc3W     = (const float*)d_in[11];
    const float* fc3b     = (const float*)d_in[12];
    float* out = (float*)d_out;

    k_prep <<<dim3(10, NB), 256>>>(features, geometry, rW1, rb1, rW2, rb2);
    k_main <<<dim3(9,  NB), 256>>>();
    k_head <<<NB, 256>>>(fc1W, fc1b, fc2W, fc2b, fc3W, fc3b, out);
}

// round 10
// speedup vs baseline: 1.3635x; 1.0187x over previous
#include <cuda_runtime.h>

#define NB 32      // batch
#define NA 286     // atoms
#define CIN 23
#define HH 100     // hidden width of radial MLP
#define BPAD 288   // padded atom count
#define NODES 512  // r-table nodes over [0, RMAX]
#define RMAX 4.5f  // all basis functions are exactly 0 at r >= 4.5

// ---------------- device scratch ----------------
__device__ float  g_gT[NB][HH][BPAD];     // g[z][k][b] = sum_j rW2[k,j]*features[z,b,j] (0-padded b)
__device__ float  g_V[HH][NODES];         // V[k][ir] = relu(h_k(r_ir))
__device__ float  g_T[NB][BPAD][NODES];   // T[z][b][ir] = sum_k V[k][ir] * g[z][k][b]  (18.9 MB)
__device__ float  g_cz[NB];
__device__ float4 g_geom4[NB][BPAD];      // (x,y,z,0), zero-padded
__device__ float  g_feats[NB][NA];

// ---------------- prep: g, cz, geom4 ----------------
__global__ void __launch_bounds__(256) k_prep(const float* __restrict__ features,
                                              const float* __restrict__ geometry,
                                              const float* __restrict__ rW2,
                                              const float* __restrict__ rb2) {
    const int z = blockIdx.y;
    const int tid = threadIdx.x;

    if (blockIdx.x == 9) {
        for (int b = tid; b < BPAD; b += 256) {
            float4 v = make_float4(0.f, 0.f, 0.f, 0.f);
            if (b < NA) {
                const float* p = geometry + (z * NA + b) * 3;
                v.x = p[0]; v.y = p[1]; v.z = p[2];
            }
            g_geom4[z][b] = v;
        }
        __shared__ float red[256];
        float s = 0.f;
        const int TOT = NA * CIN;
        for (int i = tid; i < TOT; i += 256)
            s = fmaf(rb2[i % CIN], features[z * TOT + i], s);
        red[tid] = s;
        __syncthreads();
        for (int off = 128; off; off >>= 1) {
            if (tid < off) red[tid] += red[tid + off];
            __syncthreads();
        }
        if (tid == 0) g_cz[z] = red[0];
        return;
    }

    __shared__ float fs[32][CIN];
    __shared__ float w2s[HH * CIN];
    const int bt = blockIdx.x * 32;

    for (int i = tid; i < 32 * CIN; i += 256) {
        int b = i / CIN, j = i % CIN;
        int gb = bt + b;
        fs[b][j] = (gb < NA) ? features[(z * NA + gb) * CIN + j] : 0.f;
    }
    for (int i = tid; i < HH * CIN; i += 256) w2s[i] = rW2[i];
    __syncthreads();

    for (int i = tid; i < HH * 32; i += 256) {
        int k = i >> 5, b = i & 31;
        float s = 0.f;
        #pragma unroll
        for (int j = 0; j < CIN; j++) s = fmaf(w2s[k * CIN + j], fs[b][j], s);
        g_gT[z][k][bt + b] = s;            // pad b's get 0 (fs zero-filled)
    }
}

// ---------------- basis: cos(pi/2 * t) via even poly ----------------
__device__ __forceinline__ float cospi_half(float t) {
    float y = t * t;
    float p = fmaf(9.1926027e-4f, y, -2.0863481e-2f);
    p = fmaf(p, y,  2.5366951e-1f);
    p = fmaf(p, y, -1.2337006f);
    p = fmaf(p, y,  1.0f);
    return p;
}
__device__ __forceinline__ void basis3(float r, float& p0, float& p1, float& p2) {
    const float inv = 1.0f / 1.5f;
    float zz = r * inv;
    float t0 = 1.f - fmaxf(2.f - fmaxf(zz + 1.f, 0.f), 0.f);
    float t1 = 1.f - fmaxf(2.f - fmaxf(zz,       0.f), 0.f);
    float t2 = 1.f - fmaxf(2.f - fmaxf(zz - 1.f, 0.f), 0.f);
    p0 = cospi_half(t0);
    p1 = cospi_half(t1);
    p2 = cospi_half(t2);
}

// ---------------- V build: V[k][ir] = relu(h_k(r_ir)) ----------------
__global__ void __launch_bounds__(NODES) k_vbuild(const float* __restrict__ rW1,
                                                  const float* __restrict__ rb1) {
    const int k  = blockIdx.x;
    const int ir = threadIdx.x;
    const float DELTA = RMAX / (float)(NODES - 1);
    float r = ir * DELTA;
    float p0, p1, p2;
    basis3(r, p0, p1, p2);
    float h = fmaf(rW1[k], p0, fmaf(rW1[HH + k], p1, fmaf(rW1[2 * HH + k], p2, rb1[k])));
    g_V[k][ir] = fmaxf(h, 0.f);
}

// ---------------- table GEMM: T[z][b][ir] = sum_k g[z][k][b] * V[k][ir] ----------------
// grid (6 b-tiles of 48, 4 ir-tiles of 128, NB). 256 thr; thread micro-tile 3b x 8ir.
// K=100 processed in 2 chunks of 50 to keep static smem under 48KB.
__global__ void __launch_bounds__(256) k_tab() {
    const int z   = blockIdx.z;
    const int b0  = blockIdx.x * 48;
    const int ir0 = blockIdx.y * 128;
    const int tid = threadIdx.x;

    __shared__ float Gs[50][48];
    __shared__ float Vs[50][128];

    const int bl = (tid >> 4) * 3;      // 0..45
    const int il = (tid & 15) * 8;      // 0..120

    float acc[3][8];
    #pragma unroll
    for (int j = 0; j < 3; j++)
        #pragma unroll
        for (int q = 0; q < 8; q++) acc[j][q] = 0.f;

    #pragma unroll
    for (int chunk = 0; chunk < 2; chunk++) {
        const int kb = chunk * 50;
        __syncthreads();
        for (int i = tid; i < 50 * 48; i += 256)
            Gs[i / 48][i % 48] = g_gT[z][kb + i / 48][b0 + (i % 48)];
        for (int i = tid; i < 50 * 128; i += 256)
            Vs[i >> 7][i & 127] = g_V[kb + (i >> 7)][ir0 + (i & 127)];
        __syncthreads();

        #pragma unroll 5
        for (int k = 0; k < 50; k++) {
            float4 v0 = *(const float4*)&Vs[k][il];
            float4 v1 = *(const float4*)&Vs[k][il + 4];
            float gb0 = Gs[k][bl], gb1 = Gs[k][bl + 1], gb2 = Gs[k][bl + 2];
            float vv[8] = {v0.x, v0.y, v0.z, v0.w, v1.x, v1.y, v1.z, v1.w};
            #pragma unroll
            for (int q = 0; q < 8; q++) {
                acc[0][q] = fmaf(gb0, vv[q], acc[0][q]);
                acc[1][q] = fmaf(gb1, vv[q], acc[1][q]);
                acc[2][q] = fmaf(gb2, vv[q], acc[2][q]);
            }
        }
    }

    #pragma unroll
    for (int j = 0; j < 3; j++) {
        float* dst = &g_T[z][b0 + bl + j][ir0 + il];
        *(float4*)dst       = make_float4(acc[j][0], acc[j][1], acc[j][2], acc[j][3]);
        *(float4*)(dst + 4) = make_float4(acc[j][4], acc[j][5], acc[j][6], acc[j][7]);
    }
}

// ---------------- pair kernel: r -> table lerp -> accumulate over b ----------------
// grid (9, NB), 256 thr = 8 warps, warp handles 4 a's; lane = b within 32-tile.
__global__ void __launch_bounds__(256) k_pairs() {
    const int z    = blockIdx.y;
    const int warp = threadIdx.x >> 5;
    const int lane = threadIdx.x & 31;
    const int a0   = blockIdx.x * 32 + warp * 4;
    const float INV = (float)(NODES - 1) / RMAX;

    float ax[4], ay[4], az[4];
    #pragma unroll
    for (int u = 0; u < 4; u++) {
        int a = a0 + u; if (a > NA - 1) a = NA - 1;   // clamp; extras never written
        float4 p = g_geom4[z][a];
        ax[u] = p.x; ay[u] = p.y; az[u] = p.z;
    }

    float acc[4] = {0.f, 0.f, 0.f, 0.f};

    for (int bt = 0; bt < BPAD; bt += 32) {
        const int b = bt + lane;
        const float4 bg = g_geom4[z][b];
        const float* __restrict__ Tb = g_T[z][b];   // padded b rows are all-zero
        #pragma unroll
        for (int u = 0; u < 4; u++) {
            float dx = bg.x - ax[u], dy = bg.y - ay[u], dz = bg.z - az[u];
            float r = sqrtf(fmaf(dx, dx, fmaf(dy, dy, fmaf(dz, dz, 1e-12f))));
            float x = fminf(r * INV, 510.999f);
            int i0 = (int)x;
            float f = x - (float)i0;
            float t0 = __ldg(&Tb[i0]);
            float t1 = __ldg(&Tb[i0 + 1]);
            acc[u] = fmaf(f, t1 - t0, acc[u] + t0);
        }
    }

    #pragma unroll
    for (int u = 0; u < 4; u++) {
        #pragma unroll
        for (int off = 16; off; off >>= 1)
            acc[u] += __shfl_xor_sync(0xffffffffu, acc[u], off);
    }

    if (lane == 0) {
        const float SCALE0 = 0.28209479177387814f / 16.911534525287763f;  // Y0 / sqrt(286)
        float czs = g_cz[z];
        #pragma unroll
        for (int u = 0; u < 4; u++) {
            int a = a0 + u;
            if (a < NA) g_feats[z][a] = (acc[u] + czs) * SCALE0;
        }
    }
}

// ---------------- head MLP: 286 -> 30 -> 10 -> 1 ----------------
__global__ void __launch_bounds__(256) k_head(const float* __restrict__ fc1W,
                                              const float* __restrict__ fc1b,
                                              const float* __restrict__ fc2W,
                                              const float* __restrict__ fc2b,
                                              const float* __restrict__ fc3W,
                                              const float* __restrict__ fc3b,
                                              float* __restrict__ out) {
    const int z = blockIdx.x;
    const int tid = threadIdx.x;
    const int warp = tid >> 5;
    const int lane = tid & 31;
    __shared__ float fsh[BPAD];
    __shared__ float h1[30];
    __shared__ float h2[10];

    for (int i = tid; i < BPAD; i += 256) fsh[i] = (i < NA) ? g_feats[z][i] : 0.f;
    __syncthreads();

    for (int o = warp; o < 30; o += 8) {
        float w[9], f[9];
        #pragma unroll
        for (int kk = 0; kk < 9; kk++) {
            int idx = lane + 32 * kk;
            w[kk] = (idx < NA) ? __ldg(&fc1W[idx * 30 + o]) : 0.f;
            f[kk] = fsh[idx];
        }
        float ssum = 0.f;
        #pragma unroll
        for (int kk = 0; kk < 9; kk++) ssum = fmaf(w[kk], f[kk], ssum);
        #pragma unroll
        for (int off = 16; off; off >>= 1) ssum += __shfl_xor_sync(0xffffffffu, ssum, off);
        if (lane == 0) h1[o] = fmaxf(ssum + fc1b[o], 0.f);
    }
    __syncthreads();

    if (tid < 10) {
        float s = fc2b[tid];
        #pragma unroll
        for (int o = 0; o < 30; o++) s = fmaf(h1[o], fc2W[o * 10 + tid], s);
        h2[tid] = fmaxf(s, 0.f);
    }
    __syncthreads();

    if (tid == 0) {
        float s = fc3b[0];
        #pragma unroll
        for (int p = 0; p < 10; p++) s = fmaf(h2[p], fc3W[p], s);
        out[z] = s;
    }
}

// ---------------- launch ----------------
extern "C" void kernel_launch(void* const* d_in, const int* in_sizes, int n_in,
                              void* d_out, int out_size) {
    const float* features = (const float*)d_in[1];
    const float* geometry = (const float*)d_in[2];
    const float* rW1      = (const float*)d_in[3];
    const float* rb1      = (const float*)d_in[4];
    const float* rW2      = (const float*)d_in[5];
    const float* rb2      = (const float*)d_in[6];
    const float* fc1W     = (const float*)d_in[7];
    const float* fc1b     = (const float*)d_in[8];
    const float* fc2W     = (const float*)d_in[9];
    const float* fc2b     = (const float*)d_in[10];
    const float* fc3W     = (const float*)d_in[11];
    const float* fc3b     = (const float*)d_in[12];
    float* out = (float*)d_out;

    k_prep  <<<dim3(10, NB), 256>>>(features, geometry, rW2, rb2);
    k_vbuild<<<HH, NODES>>>(rW1, rb1);
    k_tab   <<<dim3(6, 4, NB), 256>>>();
    k_pairs <<<dim3(9, NB), 256>>>();
    k_head  <<<NB, 256>>>(fc1W, fc1b, fc2W, fc2b, fc3W, fc3b, out);
}

// round 11
// speedup vs baseline: 2.0665x; 1.5155x over previous
#include <cuda_runtime.h>

#define NB 32      // batch
#define NA 286     // atoms
#define CIN 23
#define HH 100     // hidden width of radial MLP
#define BPAD 288   // padded atom count
#define NODES 256  // r-table nodes over [0, RMAX]
#define RMAX 4.5f  // all basis functions are exactly 0 at r >= 4.5

// ---------------- device scratch ----------------
__device__ float  g_gT[NB][HH][BPAD];     // g[z][k][b] = sum_j rW2[k,j]*features[z,b,j] (0-padded b)
__device__ float  g_V[HH][NODES];         // V[k][ir] = relu(h_k(r_ir))
__device__ float  g_T[NB][BPAD][NODES];   // T[z][b][ir] = sum_k V[k][ir] * g[z][k][b]  (9.4 MB)
__device__ float  g_cz[NB];
__device__ float4 g_geom4[NB][BPAD];      // (x,y,z,0), zero-padded
__device__ float  g_feats[NB][NA];

// ---------------- prep: g, cz, geom4 ----------------
__global__ void __launch_bounds__(256) k_prep(const float* __restrict__ features,
                                              const float* __restrict__ geometry,
                                              const float* __restrict__ rW2,
                                              const float* __restrict__ rb2) {
    const int z = blockIdx.y;
    const int tid = threadIdx.x;

    if (blockIdx.x == 9) {
        for (int b = tid; b < BPAD; b += 256) {
            float4 v = make_float4(0.f, 0.f, 0.f, 0.f);
            if (b < NA) {
                const float* p = geometry + (z * NA + b) * 3;
                v.x = p[0]; v.y = p[1]; v.z = p[2];
            }
            g_geom4[z][b] = v;
        }
        __shared__ float red[256];
        float s = 0.f;
        const int TOT = NA * CIN;
        for (int i = tid; i < TOT; i += 256)
            s = fmaf(rb2[i % CIN], features[z * TOT + i], s);
        red[tid] = s;
        __syncthreads();
        for (int off = 128; off; off >>= 1) {
            if (tid < off) red[tid] += red[tid + off];
            __syncthreads();
        }
        if (tid == 0) g_cz[z] = red[0];
        return;
    }

    __shared__ float fs[32][CIN];
    __shared__ float w2s[HH * CIN];
    const int bt = blockIdx.x * 32;

    for (int i = tid; i < 32 * CIN; i += 256) {
        int b = i / CIN, j = i % CIN;
        int gb = bt + b;
        fs[b][j] = (gb < NA) ? features[(z * NA + gb) * CIN + j] : 0.f;
    }
    for (int i = tid; i < HH * CIN; i += 256) w2s[i] = rW2[i];
    __syncthreads();

    for (int i = tid; i < HH * 32; i += 256) {
        int k = i >> 5, b = i & 31;
        float s = 0.f;
        #pragma unroll
        for (int j = 0; j < CIN; j++) s = fmaf(w2s[k * CIN + j], fs[b][j], s);
        g_gT[z][k][bt + b] = s;            // pad b's get 0 (fs zero-filled)
    }
}

// ---------------- basis: cos(pi/2 * t) via even poly ----------------
__device__ __forceinline__ float cospi_half(float t) {
    float y = t * t;
    float p = fmaf(9.1926027e-4f, y, -2.0863481e-2f);
    p = fmaf(p, y,  2.5366951e-1f);
    p = fmaf(p, y, -1.2337006f);
    p = fmaf(p, y,  1.0f);
    return p;
}
__device__ __forceinline__ void basis3(float r, float& p0, float& p1, float& p2) {
    const float inv = 1.0f / 1.5f;
    float zz = r * inv;
    float t0 = 1.f - fmaxf(2.f - fmaxf(zz + 1.f, 0.f), 0.f);
    float t1 = 1.f - fmaxf(2.f - fmaxf(zz,       0.f), 0.f);
    float t2 = 1.f - fmaxf(2.f - fmaxf(zz - 1.f, 0.f), 0.f);
    p0 = cospi_half(t0);
    p1 = cospi_half(t1);
    p2 = cospi_half(t2);
}

// ---------------- V build: V[k][ir] = relu(h_k(r_ir)) ----------------
__global__ void __launch_bounds__(NODES) k_vbuild(const float* __restrict__ rW1,
                                                  const float* __restrict__ rb1) {
    const int k  = blockIdx.x;
    const int ir = threadIdx.x;
    const float DELTA = RMAX / (float)(NODES - 1);
    float r = ir * DELTA;
    float p0, p1, p2;
    basis3(r, p0, p1, p2);
    float h = fmaf(rW1[k], p0, fmaf(rW1[HH + k], p1, fmaf(rW1[2 * HH + k], p2, rb1[k])));
    g_V[k][ir] = fmaxf(h, 0.f);
}

// ---------------- table GEMM: T[z][b][ir] = sum_k g[z][k][b] * V[k][ir] ----------------
// grid (6 b-tiles of 48, 2 ir-tiles of 128, NB). 256 thr; thread micro-tile 3b x 8ir.
// K=100 processed in 2 chunks of 50 to keep static smem under 48KB.
__global__ void __launch_bounds__(256) k_tab() {
    const int z   = blockIdx.z;
    const int b0  = blockIdx.x * 48;
    const int ir0 = blockIdx.y * 128;
    const int tid = threadIdx.x;

    __shared__ float Gs[50][48];
    __shared__ float Vs[50][128];

    const int bl = (tid >> 4) * 3;      // 0..45
    const int il = (tid & 15) * 8;      // 0..120

    float acc[3][8];
    #pragma unroll
    for (int j = 0; j < 3; j++)
        #pragma unroll
        for (int q = 0; q < 8; q++) acc[j][q] = 0.f;

    #pragma unroll
    for (int chunk = 0; chunk < 2; chunk++) {
        const int kb = chunk * 50;
        __syncthreads();
        for (int i = tid; i < 50 * 48; i += 256)
            Gs[i / 48][i % 48] = g_gT[z][kb + i / 48][b0 + (i % 48)];
        for (int i = tid; i < 50 * 128; i += 256)
            Vs[i >> 7][i & 127] = g_V[kb + (i >> 7)][ir0 + (i & 127)];
        __syncthreads();

        #pragma unroll 5
        for (int k = 0; k < 50; k++) {
            float4 v0 = *(const float4*)&Vs[k][il];
            float4 v1 = *(const float4*)&Vs[k][il + 4];
            float gb0 = Gs[k][bl], gb1 = Gs[k][bl + 1], gb2 = Gs[k][bl + 2];
            float vv[8] = {v0.x, v0.y, v0.z, v0.w, v1.x, v1.y, v1.z, v1.w};
            #pragma unroll
            for (int q = 0; q < 8; q++) {
                acc[0][q] = fmaf(gb0, vv[q], acc[0][q]);
                acc[1][q] = fmaf(gb1, vv[q], acc[1][q]);
                acc[2][q] = fmaf(gb2, vv[q], acc[2][q]);
            }
        }
    }

    #pragma unroll
    for (int j = 0; j < 3; j++) {
        float* dst = &g_T[z][b0 + bl + j][ir0 + il];
        *(float4*)dst       = make_float4(acc[j][0], acc[j][1], acc[j][2], acc[j][3]);
        *(float4*)(dst + 4) = make_float4(acc[j][4], acc[j][5], acc[j][6], acc[j][7]);
    }
}

// ---------------- pair kernel: r -> table lerp -> accumulate over b ----------------
// grid (18, NB), 256 thr = 8 warps, warp handles 2 a's; lane = b within 32-tile.
// 576 blocks -> ~4 blocks/SM for latency hiding on the scattered L2 loads.
__global__ void __launch_bounds__(256) k_pairs() {
    const int z    = blockIdx.y;
    const int warp = threadIdx.x >> 5;
    const int lane = threadIdx.x & 31;
    const int a0   = blockIdx.x * 16 + warp * 2;
    const float INV = (float)(NODES - 1) / RMAX;
    const float XMAX = (float)(NODES - 2) + 0.999f;   // 254.999

    float ax[2], ay[2], az[2];
    #pragma unroll
    for (int u = 0; u < 2; u++) {
        int a = a0 + u; if (a > NA - 1) a = NA - 1;   // clamp; extras never written
        float4 p = g_geom4[z][a];
        ax[u] = p.x; ay[u] = p.y; az[u] = p.z;
    }

    float acc[2] = {0.f, 0.f};

    for (int bt = 0; bt < BPAD; bt += 32) {
        const int b = bt + lane;
        const float4 bg = g_geom4[z][b];
        const float* __restrict__ Tb = g_T[z][b];   // padded b rows are all-zero
        #pragma unroll
        for (int u = 0; u < 2; u++) {
            float dx = bg.x - ax[u], dy = bg.y - ay[u], dz = bg.z - az[u];
            float r = sqrtf(fmaf(dx, dx, fmaf(dy, dy, fmaf(dz, dz, 1e-12f))));
            float x = fminf(r * INV, XMAX);
            int i0 = (int)x;
            float f = x - (float)i0;
            float t0 = __ldg(&Tb[i0]);
            float t1 = __ldg(&Tb[i0 + 1]);
            acc[u] = fmaf(f, t1 - t0, acc[u] + t0);
        }
    }

    #pragma unroll
    for (int u = 0; u < 2; u++) {
        #pragma unroll
        for (int off = 16; off; off >>= 1)
            acc[u] += __shfl_xor_sync(0xffffffffu, acc[u], off);
    }

    if (lane == 0) {
        const float SCALE0 = 0.28209479177387814f / 16.911534525287763f;  // Y0 / sqrt(286)
        float czs = g_cz[z];
        #pragma unroll
        for (int u = 0; u < 2; u++) {
            int a = a0 + u;
            if (a < NA) g_feats[z][a] = (acc[u] + czs) * SCALE0;
        }
    }
}

// ---------------- head MLP: 286 -> 30 -> 10 -> 1 ----------------
__global__ void __launch_bounds__(256) k_head(const float* __restrict__ fc1W,
                                              const float* __restrict__ fc1b,
                                              const float* __restrict__ fc2W,
                                              const float* __restrict__ fc2b,
                                              const float* __restrict__ fc3W,
                                              const float* __restrict__ fc3b,
                                              float* __restrict__ out) {
    const int z = blockIdx.x;
    const int tid = threadIdx.x;
    const int warp = tid >> 5;
    const int lane = tid & 31;
    __shared__ float fsh[BPAD];
    __shared__ float h1[30];
    __shared__ float h2[10];

    for (int i = tid; i < BPAD; i += 256) fsh[i] = (i < NA) ? g_feats[z][i] : 0.f;
    __syncthreads();

    for (int o = warp; o < 30; o += 8) {
        float w[9], f[9];
        #pragma unroll
        for (int kk = 0; kk < 9; kk++) {
            int idx = lane + 32 * kk;
            w[kk] = (idx < NA) ? __ldg(&fc1W[idx * 30 + o]) : 0.f;
            f[kk] = fsh[idx];
        }
        float ssum = 0.f;
        #pragma unroll
        for (int kk = 0; kk < 9; kk++) ssum = fmaf(w[kk], f[kk], ssum);
        #pragma unroll
        for (int off = 16; off; off >>= 1) ssum += __shfl_xor_sync(0xffffffffu, ssum, off);
        if (lane == 0) h1[o] = fmaxf(ssum + fc1b[o], 0.f);
    }
    __syncthreads();

    if (tid < 10) {
        float s = fc2b[tid];
        #pragma unroll
        for (int o = 0; o < 30; o++) s = fmaf(h1[o], fc2W[o * 10 + tid], s);
        h2[tid] = fmaxf(s, 0.f);
    }
    __syncthreads();

    if (tid == 0) {
        float s = fc3b[0];
        #pragma unroll
        for (int p = 0; p < 10; p++) s = fmaf(h2[p], fc3W[p], s);
        out[z] = s;
    }
}

// ---------------- launch ----------------
extern "C" void kernel_launch(void* const* d_in, const int* in_sizes, int n_in,
                              void* d_out, int out_size) {
    const float* features = (const float*)d_in[1];
    const float* geometry = (const float*)d_in[2];
    const float* rW1      = (const float*)d_in[3];
    const float* rb1      = (const float*)d_in[4];
    const float* rW2      = (const float*)d_in[5];
    const float* rb2      = (const float*)d_in[6];
    const float* fc1W     = (const float*)d_in[7];
    const float* fc1b     = (const float*)d_in[8];
    const float* fc2W     = (const float*)d_in[9];
    const float* fc2b     = (const float*)d_in[10];
    const float* fc3W     = (const float*)d_in[11];
    const float* fc3b     = (const float*)d_in[12];
    float* out = (float*)d_out;

    k_prep  <<<dim3(10, NB), 256>>>(features, geometry, rW2, rb2);
    k_vbuild<<<HH, NODES>>>(rW1, rb1);
    k_tab   <<<dim3(6, 2, NB), 256>>>();
    k_pairs <<<dim3(18, NB), 256>>>();
    k_head  <<<NB, 256>>>(fc1W, fc1b, fc2W, fc2b, fc3W, fc3b, out);
}